// round 4
// baseline (speedup 1.0000x reference)
#include <cuda_runtime.h>
#include <cuda_bf16.h>
#include <cstdint>

// Problem constants (fixed shapes per reference setup_inputs)
#define IN_CH        10
#define OUT_CH       32
#define NUM_PILLARS  50000
#define EPS          1e-3f
#define TPB          256
#define PPB          256   // points per block (8 warps x 32 points)

// Scratch (device globals: allocation-free, graph-safe)
__device__ __align__(128) float g_Wf[IN_CH * OUT_CH];          // folded W, [k][c]
__device__ __align__(128) float g_bf[OUT_CH];                  // folded bias
__device__ __align__(128) float g_pmax[NUM_PILLARS * OUT_CH];  // pillar max (6.4 MB)

// ---------------------------------------------------------------------------
// Kernel 1: zero pillar-max buffer; block 0 additionally folds BN into W.
//   x_bn = in @ (W*s)^T + (beta - mean*s),  s = gamma * rsqrt(var+eps)
// ---------------------------------------------------------------------------
__global__ void prep_kernel(const float* __restrict__ W,
                            const float* __restrict__ gamma,
                            const float* __restrict__ beta,
                            const float* __restrict__ mean,
                            const float* __restrict__ var) {
    if (blockIdx.x == 0 && threadIdx.x < OUT_CH) {
        int c = threadIdx.x;
        float s = rsqrtf(var[c] + EPS) * gamma[c];
#pragma unroll
        for (int k = 0; k < IN_CH; k++)
            g_Wf[k * OUT_CH + c] = W[c * IN_CH + k] * s;
        g_bf[c] = beta[c] - mean[c] * s;
    }
    int i = blockIdx.x * blockDim.x + threadIdx.x;
    const int n4 = (NUM_PILLARS * OUT_CH) / 4;
    if (i < n4)
        reinterpret_cast<float4*>(g_pmax)[i] = make_float4(0.f, 0.f, 0.f, 0.f);
}

// ---------------------------------------------------------------------------
// Kernel 2: main pass.  8 lanes x float4 channels == 4 points per warp
// instruction; 8 independent iterations cover the warp's 32 points.
//   - input rows loaded directly (5x float2, 8-lane broadcast per group)
//   - per-thread 4-channel weight columns in registers
//   - ReLU, evict-first STG.128 of out[i, c0:c0+4]
//   - snapshot-guarded atomicMax into L2-resident pillar buffer
// ---------------------------------------------------------------------------
__global__ __launch_bounds__(TPB) void pfn_main_kernel(
    const float* __restrict__ in,
    const int*   __restrict__ inv,
    float*       __restrict__ out,
    int n) {
    const int t    = threadIdx.x;
    const int lane = t & 31;
    const int warp = t >> 5;
    const int c0   = (lane & 7) * 4;       // this thread's 4 channels
    const int pofs = lane >> 3;            // point offset within 4-group
    const int pbase = blockIdx.x * PPB + warp * 32;

    // per-thread folded weight columns + bias (4 channels)
    float4 wv[IN_CH];
#pragma unroll
    for (int k = 0; k < IN_CH; k++)
        wv[k] = *reinterpret_cast<const float4*>(&g_Wf[k * OUT_CH + c0]);
    const float4 bv = *reinterpret_cast<const float4*>(&g_bf[c0]);

#pragma unroll
    for (int it = 0; it < 8; it++) {
        const int i = pbase + it * 4 + pofs;
        if (i < n) {
            // pillar index: 8 lanes/group same address -> broadcast LDG (L1)
            const int p = inv[i];

            // input row: 40B, 8B-aligned -> 5x float2 broadcast loads
            const float2* xr = reinterpret_cast<const float2*>(in + (size_t)i * IN_CH);
            float xk[IN_CH];
#pragma unroll
            for (int h = 0; h < 5; h++) {
                float2 v = xr[h];
                xk[2 * h]     = v.x;
                xk[2 * h + 1] = v.y;
            }

            float4 acc = bv;
#pragma unroll
            for (int k = 0; k < IN_CH; k++) {
                acc.x = fmaf(xk[k], wv[k].x, acc.x);
                acc.y = fmaf(xk[k], wv[k].y, acc.y);
                acc.z = fmaf(xk[k], wv[k].z, acc.z);
                acc.w = fmaf(xk[k], wv[k].w, acc.w);
            }
            acc.x = fmaxf(acc.x, 0.f); acc.y = fmaxf(acc.y, 0.f);
            acc.z = fmaxf(acc.z, 0.f); acc.w = fmaxf(acc.w, 0.f);

            // first half of output row; evict-first (keep pmax in L2)
            __stcs(reinterpret_cast<float4*>(&out[(size_t)i * 64 + c0]), acc);

            // snapshot-guarded scatter-max (values >= 0: int cmp == float cmp)
            float* pmf = &g_pmax[p * OUT_CH + c0];
            float4 cur = *reinterpret_cast<const float4*>(pmf);
            int* pm = reinterpret_cast<int*>(pmf);
            if (acc.x > cur.x) atomicMax(pm + 0, __float_as_int(acc.x));
            if (acc.y > cur.y) atomicMax(pm + 1, __float_as_int(acc.y));
            if (acc.z > cur.z) atomicMax(pm + 2, __float_as_int(acc.z));
            if (acc.w > cur.w) atomicMax(pm + 3, __float_as_int(acc.w));
        }
    }
}

// ---------------------------------------------------------------------------
// Kernel 3: gather: out[i, 32:64] = pmax[inv[i], :].  Same layout; pmax is
// L2-resident; out stores evict-first.  Iterations fully independent.
// ---------------------------------------------------------------------------
__global__ __launch_bounds__(TPB) void pfn_gather_kernel(
    const int* __restrict__ inv,
    float*     __restrict__ out,
    int n) {
    const int t    = threadIdx.x;
    const int lane = t & 31;
    const int warp = t >> 5;
    const int c0   = (lane & 7) * 4;
    const int pofs = lane >> 3;
    const int pbase = blockIdx.x * PPB + warp * 32;

#pragma unroll
    for (int it = 0; it < 8; it++) {
        const int i = pbase + it * 4 + pofs;
        if (i < n) {
            const int p = inv[i];
            float4 v = *reinterpret_cast<const float4*>(&g_pmax[p * OUT_CH + c0]);
            __stcs(reinterpret_cast<float4*>(&out[(size_t)i * 64 + 32 + c0]), v);
        }
    }
}

// ---------------------------------------------------------------------------
// Launch.  Input order: inputs, unq_inv, W, gamma, beta, running_mean,
// running_var[, num_out_inds].
// ---------------------------------------------------------------------------
extern "C" void kernel_launch(void* const* d_in, const int* in_sizes, int n_in,
                              void* d_out, int out_size) {
    const float* in    = (const float*)d_in[0];
    const int*   inv   = (const int*)d_in[1];
    const float* W     = (const float*)d_in[2];
    const float* gamma = (const float*)d_in[3];
    const float* beta  = (const float*)d_in[4];
    const float* mean  = (const float*)d_in[5];
    const float* var   = (const float*)d_in[6];
    float* out = (float*)d_out;

    const int n = in_sizes[1];  // number of points (unq_inv element count)

    const int n4 = (NUM_PILLARS * OUT_CH) / 4;
    prep_kernel<<<(n4 + TPB - 1) / TPB, TPB>>>(W, gamma, beta, mean, var);

    const int nBlocks = (n + PPB - 1) / PPB;
    pfn_main_kernel<<<nBlocks, TPB>>>(in, inv, out, n);

    pfn_gather_kernel<<<nBlocks, TPB>>>(inv, out, n);
}